// round 3
// baseline (speedup 1.0000x reference)
#include <cuda_runtime.h>

#define BB   128   // batch
#define VV   256   // vertices
#define FF   64    // features
#define FE   128   // effective features (x ++ mean)
#define NS   4     // spatial dims
#define NLR  64    // learned-rep dims
#define NSLR 68    // NS + NLR
#define KNB  40    // neighbors
#define NOUT 128   // output features

// ---------------- scratch (static device globals; no allocation) ------------
__device__ float g_mx  [BB * FF];            // per-batch mean of x
__device__ float g_s   [BB * VV * NS];       // spatial coords
__device__ float g_lr  [BB * VV * NLR];      // learned reps
__device__ float g_mean[BB * VV * NLR];      // ft.mean over K
__device__ float g_max [BB * VV * NLR];      // ft.max  over K

// ---------------- K1: per-batch mean over vertices ---------------------------
__global__ void k_mean(const float* __restrict__ x) {
    int b = blockIdx.x;           // 0..127
    int f = threadIdx.x;          // 0..63
    const float* xb = x + (size_t)b * VV * FF + f;
    float acc = 0.f;
    #pragma unroll 8
    for (int v = 0; v < VV; v++) acc += xb[v * FF];
    g_mx[b * FF + f] = acc * (1.0f / VV);
}

// ---------------- K2: slr = relu(x_cat @ W_slr + b_slr) ---------------------
__global__ void k_slr(const float* __restrict__ x,
                      const float* __restrict__ W,
                      const float* __restrict__ bias) {
    int bv = blockIdx.x;          // 0..B*V-1
    int b  = bv >> 8;             // V = 256
    int t  = threadIdx.x;         // 0..127
    __shared__ float xr[FE];
    xr[t] = (t < FF) ? x[(size_t)bv * FF + t] : g_mx[b * FF + (t - FF)];
    __syncthreads();
    if (t < NSLR) {
        float acc = bias[t];
        #pragma unroll 8
        for (int r = 0; r < FE; r++) acc += xr[r] * W[r * NSLR + t];
        acc = fmaxf(acc, 0.f);
        if (t < NS) g_s [bv * NS  + t]        = acc;
        else        g_lr[bv * NLR + (t - NS)] = acc;
    }
}

// ---------------- K3: kNN selection + weighted mean/max aggregation ---------
// one block per batch, thread i owns row i
#define LRP 68                     // padded lr row stride
#define SMEM3 ((VV * LRP + VV * NS) * 4)

// lexicographic max-heap ordering on (value, index): ties in value broken by
// LARGER index = "greater". Root holds the lexicographic max, so among tied
// d2 the largest index is evicted first -> matches jax.lax.top_k stability.
__device__ __forceinline__ bool pair_gt(float av, int ai, float bv, int bi) {
    return (av > bv) || (av == bv && ai > bi);
}

__device__ __forceinline__ void heap_sift(float* hv, int* hi, int root) {
    float v = hv[root]; int ix = hi[root];
    int r = root;
    while (true) {
        int c = 2 * r + 1;
        if (c >= KNB) break;
        if (c + 1 < KNB && pair_gt(hv[c + 1], hi[c + 1], hv[c], hi[c])) c++;
        if (!pair_gt(hv[c], hi[c], v, ix)) break;
        hv[r] = hv[c]; hi[r] = hi[c]; r = c;
    }
    hv[r] = v; hi[r] = ix;
}

__global__ void k_knn() {
    extern __shared__ float sh[];
    float* lr_sh = sh;                 // [VV][LRP]
    float* s_sh  = sh + VV * LRP;      // [VV][4]
    int b = blockIdx.x;
    int i = threadIdx.x;               // 0..255 (row)

    // stage lr for this batch into shared (padded rows)
    const float* lrg = g_lr + (size_t)b * VV * NLR;
    for (int idx = i; idx < VV * NLR; idx += VV) {
        int r = idx >> 6, c = idx & 63;
        lr_sh[r * LRP + c] = lrg[idx];
    }
    // stage s
    float4 sv = ((const float4*)(g_s + (size_t)b * VV * NS))[i];
    ((float4*)s_sh)[i] = sv;
    __syncthreads();

    const float s0 = sv.x, s1 = sv.y, s2 = sv.z, s3 = sv.w;

    // --- top-K smallest (d2, idx) via per-thread lexicographic max-heap ---
    float hv[KNB];
    int   hi[KNB];
    #pragma unroll
    for (int j = 0; j < KNB; j++) {
        float4 sj = ((const float4*)s_sh)[j];
        float dx = s0 - sj.x, dy = s1 - sj.y, dz = s2 - sj.z, dw = s3 - sj.w;
        hv[j] = dx*dx + dy*dy + dz*dz + dw*dw;
        hi[j] = j;
    }
    for (int r = KNB / 2 - 1; r >= 0; --r) heap_sift(hv, hi, r);
    for (int j = KNB; j < VV; j++) {
        float4 sj = ((const float4*)s_sh)[j];
        float dx = s0 - sj.x, dy = s1 - sj.y, dz = s2 - sj.z, dw = s3 - sj.w;
        float d2 = dx*dx + dy*dy + dz*dz + dw*dw;
        // j > every index in the heap, so on a d2 tie the new pair is
        // lexicographically larger -> strict < is exactly right.
        if (d2 < hv[0]) { hv[0] = d2; hi[0] = j; heap_sift(hv, hi, 0); }
    }
    // weights
    for (int k = 0; k < KNB; k++) hv[k] = __expf(-10.0f * hv[k]);

    // --- aggregation: mean and max of lr[idx]*w over K, f chunked by 16 ---
    float* om = g_mean + ((size_t)b * VV + i) * NLR;
    float* ox = g_max  + ((size_t)b * VV + i) * NLR;
    #pragma unroll
    for (int c0 = 0; c0 < NLR; c0 += 16) {
        float m[16], mx[16];
        #pragma unroll
        for (int f = 0; f < 16; f++) { m[f] = 0.f; mx[f] = 0.f; }
        for (int k = 0; k < KNB; k++) {
            int   j = hi[k];
            float w = hv[k];
            const float4* row = (const float4*)&lr_sh[j * LRP + c0];
            #pragma unroll
            for (int q = 0; q < 4; q++) {
                float4 lv = row[q];
                float v0 = lv.x * w, v1 = lv.y * w, v2 = lv.z * w, v3 = lv.w * w;
                m [q*4+0] += v0; m [q*4+1] += v1; m [q*4+2] += v2; m [q*4+3] += v3;
                mx[q*4+0] = fmaxf(mx[q*4+0], v0);
                mx[q*4+1] = fmaxf(mx[q*4+1], v1);
                mx[q*4+2] = fmaxf(mx[q*4+2], v2);
                mx[q*4+3] = fmaxf(mx[q*4+3], v3);
            }
        }
        #pragma unroll
        for (int f = 0; f < 16; f++) {
            om[c0 + f] = m[f] * (1.0f / KNB);
            ox[c0 + f] = mx[f];
        }
    }
}

// ---------------- K4: out = relu(fp @ W_out + b_out) ------------------------
// fp = [x(64) | mx(64) | mean(64) | max(64)]; 8 rows per block, 128 threads.
#define ROWS4 8
__global__ void k_out(const float* __restrict__ x,
                      const float* __restrict__ W,
                      const float* __restrict__ bias,
                      float* __restrict__ out) {
    __shared__ float fp[ROWS4][256];
    int t   = threadIdx.x;                 // 0..127 = output column
    int bv0 = blockIdx.x * ROWS4;          // first row (all rows in same batch)
    int b   = bv0 >> 8;

    for (int idx = t; idx < ROWS4 * 256; idx += 128) {
        int row = idx >> 8, c = idx & 255;
        int bv  = bv0 + row;
        float val;
        if      (c < 64)  val = x     [(size_t)bv * FF + c];
        else if (c < 128) val = g_mx  [b * FF + (c - 64)];
        else if (c < 192) val = g_mean[(size_t)bv * NLR + (c - 128)];
        else              val = g_max [(size_t)bv * NLR + (c - 192)];
        fp[row][c] = val;
    }
    __syncthreads();

    float acc[ROWS4];
    #pragma unroll
    for (int r = 0; r < ROWS4; r++) acc[r] = 0.f;

    for (int r = 0; r < 256; r += 4) {
        float4 fv[ROWS4];
        #pragma unroll
        for (int row = 0; row < ROWS4; row++)
            fv[row] = *(const float4*)&fp[row][r];
        #pragma unroll
        for (int rr = 0; rr < 4; rr++) {
            float w = W[(r + rr) * NOUT + t];
            #pragma unroll
            for (int row = 0; row < ROWS4; row++) {
                float fval = (rr == 0) ? fv[row].x : (rr == 1) ? fv[row].y
                           : (rr == 2) ? fv[row].z : fv[row].w;
                acc[row] += fval * w;
            }
        }
    }
    float bo = bias[t];
    #pragma unroll
    for (int row = 0; row < ROWS4; row++)
        out[(size_t)(bv0 + row) * NOUT + t] = fmaxf(acc[row] + bo, 0.f);
}

// ---------------- launch ------------------------------------------------------
extern "C" void kernel_launch(void* const* d_in, const int* in_sizes, int n_in,
                              void* d_out, int out_size) {
    const float* x     = (const float*)d_in[0];
    const float* W_slr = (const float*)d_in[1];
    const float* b_slr = (const float*)d_in[2];
    const float* W_out = (const float*)d_in[3];
    const float* b_out = (const float*)d_in[4];
    float* out = (float*)d_out;

    cudaFuncSetAttribute(k_knn, cudaFuncAttributeMaxDynamicSharedMemorySize, SMEM3);

    k_mean<<<BB, FF>>>(x);
    k_slr <<<BB * VV, 128>>>(x, W_slr, b_slr);
    k_knn <<<BB, VV, SMEM3>>>();
    k_out <<<BB * VV / ROWS4, 128>>>(x, W_out, b_out, out);
}

// round 4
// speedup vs baseline: 4.5183x; 4.5183x over previous
#include <cuda_runtime.h>

#define BB   128
#define VV   256
#define FF   64
#define NS   4
#define NLR  64
#define NSLR 68
#define KNB  40
#define NOUT 128

// ---------------- scratch ----------------------------------------------------
__device__ float g_mx  [BB * FF];
__device__ float g_s   [BB * VV * NS];
__device__ float g_lr  [BB * VV * NLR];
__device__ float g_mean[BB * VV * NLR];
__device__ float g_max [BB * VV * NLR];
__device__ int   g_nidx[BB * VV * KNB];
__device__ float g_nw  [BB * VV * KNB];
__device__ float g_bb  [BB * NOUT];       // b_out + mx @ W_out[64:128]

// ============ K_FRONT: per-batch mean + slr = relu(x_cat @ W_slr + b) ========
// one block per batch, 256 threads
#define XSP 65
#define KF_SMEM ((VV * XSP + 128 * NSLR + 64 + 256 + NSLR) * 4)
__global__ void k_front(const float* __restrict__ x,
                        const float* __restrict__ W,
                        const float* __restrict__ bias) {
    extern __shared__ float sh[];
    float* xs   = sh;                       // [256][65]
    float* Wsh  = xs + VV * XSP;            // [128][68]
    float* mean = Wsh + 128 * NSLR;         // [64]
    float* red  = mean + 64;                // [256]
    float* cc   = red + 256;                // [68]
    int b = blockIdx.x;
    int t = threadIdx.x;

    // stage x (coalesced) and W
    const float* xb = x + (size_t)b * VV * FF;
    for (int e = t; e < VV * FF; e += 256) {
        int row = e >> 6, c = e & 63;
        xs[row * XSP + c] = xb[e];
    }
    for (int e = t; e < 128 * NSLR; e += 256) Wsh[e] = W[e];
    __syncthreads();

    // mean over vertices: 4 partial groups of 64 v
    {
        int f = t & 63, vg = t >> 6;
        float acc = 0.f;
        #pragma unroll 8
        for (int v = vg * 64; v < vg * 64 + 64; v++) acc += xs[v * XSP + f];
        red[vg * 64 + f] = acc;
    }
    __syncthreads();
    if (t < 64) {
        float m = (red[t] + red[64 + t] + red[128 + t] + red[192 + t]) * (1.0f / VV);
        mean[t] = m;
        g_mx[b * FF + t] = m;
    }
    __syncthreads();

    // constant (mean) half of the GEMM: cc[c] = b[c] + sum_k mean[k]*W[64+k][c]
    if (t < NSLR) {
        float acc = bias[t];
        #pragma unroll 8
        for (int k = 0; k < 64; k++) acc += mean[k] * Wsh[(64 + k) * NSLR + t];
        cc[t] = acc;
    }
    __syncthreads();

    // main GEMM: 256 rows x 68 cols, thread = 4 rows x 17 cols
    int rg = t >> 2;            // 0..63 -> rows rg*4..rg*4+3
    int cg = t & 3;             // cols cg*17..cg*17+16
    float acc[4][17];
    #pragma unroll
    for (int u = 0; u < 17; u++) {
        float c0 = cc[cg * 17 + u];
        #pragma unroll
        for (int q = 0; q < 4; q++) acc[q][u] = c0;
    }
    const float* xr = xs + (rg * 4) * XSP;
    #pragma unroll 2
    for (int k = 0; k < 64; k++) {
        float a0 = xr[k], a1 = xr[XSP + k], a2 = xr[2 * XSP + k], a3 = xr[3 * XSP + k];
        const float* wrow = Wsh + k * NSLR + cg * 17;
        #pragma unroll
        for (int u = 0; u < 17; u++) {
            float w = wrow[u];
            acc[0][u] += a0 * w; acc[1][u] += a1 * w;
            acc[2][u] += a2 * w; acc[3][u] += a3 * w;
        }
    }
    #pragma unroll
    for (int q = 0; q < 4; q++) {
        int bv = b * VV + rg * 4 + q;
        #pragma unroll
        for (int u = 0; u < 17; u++) {
            int col = cg * 17 + u;
            float v = fmaxf(acc[q][u], 0.f);
            if (col < NS) g_s[bv * NS + col];
            if (col < NS) g_s [bv * NS  + col]       = v;
            else          g_lr[bv * NLR + col - NS]  = v;
        }
    }
}

// ============ K_SEL: warp-per-row top-40 by (d2, idx), ballot binary search ==
// grid = BB*VV/8 blocks, 256 threads (8 warps, one row each)
__global__ void k_sel() {
    __shared__ float4 s_sh[VV];
    int b = blockIdx.x >> 5;
    int i = ((blockIdx.x & 31) << 3) + (threadIdx.x >> 5);
    int l = threadIdx.x & 31;
    if (threadIdx.x < VV)
        s_sh[threadIdx.x] = ((const float4*)g_s)[b * VV + threadIdx.x];
    __syncthreads();

    float4 sv = s_sh[i];
    float d2[8]; unsigned bits[8];
    #pragma unroll
    for (int q = 0; q < 8; q++) {
        float4 sj = s_sh[q * 32 + l];
        float dx = sv.x - sj.x, dy = sv.y - sj.y, dz = sv.z - sj.z, dw = sv.w - sj.w;
        d2[q] = dx * dx + dy * dy + dz * dz + dw * dw;
        bits[q] = __float_as_uint(d2[q]);   // d2 >= 0 -> monotonic as uint
    }
    // smallest t with count(bits <= t) >= 40
    unsigned lo = 0u, hi = 0xFFFFFFFFu;
    #pragma unroll 1
    for (int it = 0; it < 32; it++) {
        unsigned mid = lo + ((hi - lo) >> 1);
        int c = 0;
        #pragma unroll
        for (int q = 0; q < 8; q++) c += (bits[q] <= mid);
        c = __reduce_add_sync(0xFFFFFFFFu, c);
        if (c >= KNB) hi = mid; else lo = mid + 1u;
    }
    unsigned thr = lo;
    int cl = 0;
    #pragma unroll
    for (int q = 0; q < 8; q++) cl += (bits[q] < thr);
    cl = __reduce_add_sync(0xFFFFFFFFu, cl);
    int need = KNB - cl;
    // among ties: smallest J with count(idx <= J) >= need (top_k stability)
    int jlo = 0, jhi = VV - 1;
    #pragma unroll 1
    for (int it = 0; it < 8; it++) {
        int jm = (jlo + jhi) >> 1;
        int c = 0;
        #pragma unroll
        for (int q = 0; q < 8; q++) c += (bits[q] == thr && (q * 32 + l) <= jm);
        c = __reduce_add_sync(0xFFFFFFFFu, c);
        if (c >= need) jhi = jm; else jlo = jm + 1;
    }
    int jthr = jlo;

    // compact & emit (idx, weight)
    int row = b * VV + i;
    int base = 0;
    #pragma unroll
    for (int q = 0; q < 8; q++) {
        int j = q * 32 + l;
        bool sel = (bits[q] < thr) || (bits[q] == thr && j <= jthr);
        unsigned bal = __ballot_sync(0xFFFFFFFFu, sel);
        if (sel) {
            int pos = base + __popc(bal & ((1u << l) - 1u));
            g_nidx[row * KNB + pos] = j;
            g_nw  [row * KNB + pos] = __expf(-10.0f * d2[q]);
        }
        base += __popc(bal);
    }
}

// ============ K_AGG: weighted mean/max gather, block per batch ===============
#define LRP 68
#define SIP 257
#define KA_SMEM ((VV * LRP + 2 * KNB * SIP) * 4)
__global__ void k_agg() {
    extern __shared__ float sh[];
    float* lr_sh = sh;                       // [256][68]
    float* sw    = sh + VV * LRP;            // [40][257]
    int*   sidx  = (int*)(sw + KNB * SIP);   // [40][257]
    int b = blockIdx.x;
    int i = threadIdx.x;

    const float* lrg = g_lr + (size_t)b * VV * NLR;
    for (int e = i; e < VV * NLR; e += VV) {
        int r = e >> 6, c = e & 63;
        lr_sh[r * LRP + c] = lrg[e];
    }
    const int*   gi = g_nidx + (size_t)b * VV * KNB;
    const float* gw = g_nw   + (size_t)b * VV * KNB;
    for (int e = i; e < VV * KNB; e += VV) {
        int r = e / KNB, k = e - r * KNB;
        sidx[k * SIP + r] = gi[e];
        sw  [k * SIP + r] = gw[e];
    }
    __syncthreads();

    float* om = g_mean + ((size_t)b * VV + i) * NLR;
    float* ox = g_max  + ((size_t)b * VV + i) * NLR;
    #pragma unroll
    for (int c0 = 0; c0 < NLR; c0 += 16) {
        float m[16], mx[16];
        #pragma unroll
        for (int f = 0; f < 16; f++) { m[f] = 0.f; mx[f] = 0.f; }
        for (int k = 0; k < KNB; k++) {
            int   j = sidx[k * SIP + i];
            float w = sw  [k * SIP + i];
            const float4* rowp = (const float4*)&lr_sh[j * LRP + c0];
            #pragma unroll
            for (int qq = 0; qq < 4; qq++) {
                float4 lv = rowp[qq];
                float v0 = lv.x * w, v1 = lv.y * w, v2 = lv.z * w, v3 = lv.w * w;
                m [qq*4+0] += v0; m [qq*4+1] += v1; m [qq*4+2] += v2; m [qq*4+3] += v3;
                mx[qq*4+0] = fmaxf(mx[qq*4+0], v0);
                mx[qq*4+1] = fmaxf(mx[qq*4+1], v1);
                mx[qq*4+2] = fmaxf(mx[qq*4+2], v2);
                mx[qq*4+3] = fmaxf(mx[qq*4+3], v3);
            }
        }
        #pragma unroll
        for (int f = 0; f < 16; f++) {
            om[c0 + f] = m[f] * (1.0f / KNB);
            ox[c0 + f] = mx[f];
        }
    }
}

// ============ K_BIAS: per-batch constant part of output GEMM =================
__global__ void k_bias(const float* __restrict__ W, const float* __restrict__ bias) {
    int b = blockIdx.x, c = threadIdx.x;
    float acc = bias[c];
    const float* wr = W + 64 * NOUT + c;
    const float* mxp = g_mx + b * FF;
    #pragma unroll 16
    for (int k = 0; k < 64; k++) acc += mxp[k] * wr[k * NOUT];
    g_bb[b * NOUT + c] = acc;
}

// ============ K_OUT: out = relu(fp @ W + bb), 64 rows x 128 cols per block ===
#define KOUT 192
#define FPP  193
#define KO_SMEM ((64 * FPP + KOUT * NOUT + NOUT) * 4)
__global__ void k_out(const float* __restrict__ x,
                      const float* __restrict__ W,
                      float* __restrict__ out) {
    extern __shared__ float sh[];
    float* fps = sh;                    // [64][193]
    float* Ws  = fps + 64 * FPP;        // [192][128]
    float* bbs = Ws + KOUT * NOUT;      // [128]
    int t   = threadIdx.x;
    int bv0 = blockIdx.x * 64;
    int b   = bv0 >> 8;

    for (int e = t; e < 64 * KOUT; e += 256) {
        int row = e / KOUT, c = e - row * KOUT;
        int bv  = bv0 + row;
        float v;
        if      (c < 64)  v = x     [(size_t)bv * FF  + c];
        else if (c < 128) v = g_mean[(size_t)bv * NLR + (c - 64)];
        else              v = g_max [(size_t)bv * NLR + (c - 128)];
        fps[row * FPP + c] = v;
    }
    for (int e = t; e < KOUT * NOUT; e += 256) {
        int k = e >> 7;
        int src = (k < 64) ? k : (k + 64);      // skip mx block (precomputed)
        Ws[e] = W[src * NOUT + (e & 127)];
    }
    if (t < NOUT) bbs[t] = g_bb[b * NOUT + t];
    __syncthreads();

    int rg = t >> 4;   // 16 rowgrps x 4 rows
    int cg = t & 15;   // 16 colgrps x 8 cols
    float acc[4][8];
    #pragma unroll
    for (int u = 0; u < 8; u++) {
        float c0 = bbs[cg * 8 + u];
        #pragma unroll
        for (int q = 0; q < 4; q++) acc[q][u] = c0;
    }
    const float* fpr = fps + (rg * 4) * FPP;
    #pragma unroll 2
    for (int k = 0; k < KOUT; k++) {
        float a0 = fpr[k], a1 = fpr[FPP + k], a2 = fpr[2 * FPP + k], a3 = fpr[3 * FPP + k];
        float4 w0 = *(const float4*)&Ws[k * NOUT + cg * 8];
        float4 w1 = *(const float4*)&Ws[k * NOUT + cg * 8 + 4];
        acc[0][0] += a0*w0.x; acc[0][1] += a0*w0.y; acc[0][2] += a0*w0.z; acc[0][3] += a0*w0.w;
        acc[0][4] += a0*w1.x; acc[0][5] += a0*w1.y; acc[0][6] += a0*w1.z; acc[0][7] += a0*w1.w;
        acc[1][0] += a1*w0.x; acc[1][1] += a1*w0.y; acc[1][2] += a1*w0.z; acc[1][3] += a1*w0.w;
        acc[1][4] += a1*w1.x; acc[1][5] += a1*w1.y; acc[1][6] += a1*w1.z; acc[1][7] += a1*w1.w;
        acc[2][0] += a2*w0.x; acc[2][1] += a2*w0.y; acc[2][2] += a2*w0.z; acc[2][3] += a2*w0.w;
        acc[2][4] += a2*w1.x; acc[2][5] += a2*w1.y; acc[2][6] += a2*w1.z; acc[2][7] += a2*w1.w;
        acc[3][0] += a3*w0.x; acc[3][1] += a3*w0.y; acc[3][2] += a3*w0.z; acc[3][3] += a3*w0.w;
        acc[3][4] += a3*w1.x; acc[3][5] += a3*w1.y; acc[3][6] += a3*w1.z; acc[3][7] += a3*w1.w;
    }
    #pragma unroll
    for (int q = 0; q < 4; q++) {
        float4 o0, o1;
        o0.x = fmaxf(acc[q][0], 0.f); o0.y = fmaxf(acc[q][1], 0.f);
        o0.z = fmaxf(acc[q][2], 0.f); o0.w = fmaxf(acc[q][3], 0.f);
        o1.x = fmaxf(acc[q][4], 0.f); o1.y = fmaxf(acc[q][5], 0.f);
        o1.z = fmaxf(acc[q][6], 0.f); o1.w = fmaxf(acc[q][7], 0.f);
        float* op = out + (size_t)(bv0 + rg * 4 + q) * NOUT + cg * 8;
        ((float4*)op)[0] = o0;
        ((float4*)op)[1] = o1;
    }
}

// ---------------- launch ------------------------------------------------------
extern "C" void kernel_launch(void* const* d_in, const int* in_sizes, int n_in,
                              void* d_out, int out_size) {
    const float* x     = (const float*)d_in[0];
    const float* W_slr = (const float*)d_in[1];
    const float* b_slr = (const float*)d_in[2];
    const float* W_out = (const float*)d_in[3];
    const float* b_out = (const float*)d_in[4];
    float* out = (float*)d_out;

    static bool attr_done = false;
    if (!attr_done) {
        cudaFuncSetAttribute(k_front, cudaFuncAttributeMaxDynamicSharedMemorySize, KF_SMEM);
        cudaFuncSetAttribute(k_agg,   cudaFuncAttributeMaxDynamicSharedMemorySize, KA_SMEM);
        cudaFuncSetAttribute(k_out,   cudaFuncAttributeMaxDynamicSharedMemorySize, KO_SMEM);
        attr_done = true;
    }

    k_front<<<BB, 256, KF_SMEM>>>(x, W_slr, b_slr);
    k_sel  <<<BB * VV / 8, 256>>>();
    k_agg  <<<BB, VV, KA_SMEM>>>();
    k_bias <<<BB, NOUT>>>(W_out, b_out);
    k_out  <<<BB * VV / 64, 256, KO_SMEM>>>(x, W_out, out);
}